// round 2
// baseline (speedup 1.0000x reference)
#include <cuda_runtime.h>

// LightGCN on GB300.
// Build CSR indexed by dst (atomic count -> block scan -> scatter),
// precompute per-edge norm, then 3 atomic-free propagate layers:
// one warp per destination node, 32 lanes = the d=32 embedding row.
// x (300k x 32 fp32 = 38.4MB) fits in L2, so gathers run at L2 bandwidth.
// NOTE: edge_index is int32 (JAX x64 disabled downgrades jnp.int64).

#define D       32
#define NMAX    300032
#define EMAX    5000064
#define SCAN_B  1024

__device__ float g_xa[NMAX * D];   // ping
__device__ float g_xb[NMAX * D];   // pong
__device__ int   g_degi[NMAX];
__device__ float g_degf[NMAX];
__device__ int   g_ptr[NMAX + 1];
__device__ int   g_cursor[NMAX];
__device__ int   g_srcs[EMAX];
__device__ float g_norms[EMAX];
__device__ int   g_bsum[SCAN_B];
__device__ int   g_boff[SCAN_B];

// x0 = concat(user_emb, item_emb); acc (d_out) = x0; zero degree counters
__global__ void k_init(const float* __restrict__ ue, const float* __restrict__ ie,
                       float* __restrict__ out, int n_users, int n) {
    int i = blockIdx.x * blockDim.x + threadIdx.x;
    int total = n * D;
    if (i < total) {
        int uend = n_users * D;
        float v = (i < uend) ? ue[i] : ie[i - uend];
        g_xa[i] = v;
        out[i]  = v;
    }
    if (i < n) g_degi[i] = 0;
}

// in-degree of each node over dst (edge_index row 1)
__global__ void k_count(const int* __restrict__ ei, int E) {
    int e = blockIdx.x * blockDim.x + threadIdx.x;
    if (e < E) {
        int dd = ei[E + e];
        if (dd >= 0 && dd < NMAX) atomicAdd(&g_degi[dd], 1);
    }
}

// block-level scan -> exclusive partials in g_ptr, block totals in g_bsum
__global__ void k_scan1(int n) {
    __shared__ int sh[SCAN_B];
    int gid = blockIdx.x * SCAN_B + threadIdx.x;
    int v = (gid < n) ? g_degi[gid] : 0;
    sh[threadIdx.x] = v;
    __syncthreads();
    for (int off = 1; off < SCAN_B; off <<= 1) {
        int t = (threadIdx.x >= off) ? sh[threadIdx.x - off] : 0;
        __syncthreads();
        sh[threadIdx.x] += t;
        __syncthreads();
    }
    if (gid < n) g_ptr[gid] = sh[threadIdx.x] - v;   // exclusive within block
    if (threadIdx.x == SCAN_B - 1) g_bsum[blockIdx.x] = sh[SCAN_B - 1];
}

// scan of block totals (nb <= 1024)
__global__ void k_scan2(int nb) {
    __shared__ int sh[SCAN_B];
    int v = ((int)threadIdx.x < nb) ? g_bsum[threadIdx.x] : 0;
    sh[threadIdx.x] = v;
    __syncthreads();
    for (int off = 1; off < SCAN_B; off <<= 1) {
        int t = (threadIdx.x >= off) ? sh[threadIdx.x - off] : 0;
        __syncthreads();
        sh[threadIdx.x] += t;
        __syncthreads();
    }
    g_boff[threadIdx.x] = sh[threadIdx.x] - v;       // exclusive block offsets
}

// add block offsets; init cursor; float degrees; sentinel ptr[n]=E
__global__ void k_scan3(int n, int E) {
    int gid = blockIdx.x * SCAN_B + threadIdx.x;
    if (gid < n) {
        int p = g_ptr[gid] + g_boff[blockIdx.x];
        g_ptr[gid]    = p;
        g_cursor[gid] = p;
        g_degf[gid]   = (float)g_degi[gid];
    }
    if (gid == n) g_ptr[n] = E;
}

// counting-sort scatter: place (src, norm) into the dst bucket
__global__ void k_scatter(const int* __restrict__ ei, int E) {
    int e = blockIdx.x * blockDim.x + threadIdx.x;
    if (e >= E) return;
    int s  = ei[e];
    int dd = ei[E + e];
    if (s < 0 || s >= NMAX || dd < 0 || dd >= NMAX) return;
    int pos = atomicAdd(&g_cursor[dd], 1);
    g_srcs[pos] = s;
    float dp = g_degf[s] * g_degf[dd];
    g_norms[pos] = (dp > 0.f) ? rsqrtf(dp) : 0.f;
}

// one propagate layer: warp per dst node, lane = column. acc += x_new.
__global__ void k_prop(int sel, float* __restrict__ acc, int n) {
    int w    = (blockIdx.x * blockDim.x + threadIdx.x) >> 5;
    int lane = threadIdx.x & 31;
    if (w >= n) return;
    const float* __restrict__ xin = sel ? g_xb : g_xa;
    float*       __restrict__ xout = sel ? g_xa : g_xb;
    int i = g_ptr[w], end = g_ptr[w + 1];
    float a = 0.f;
    // unroll 4 edges for MLP against L2 latency
    for (; i + 4 <= end; i += 4) {
        int   s0 = g_srcs[i],     s1 = g_srcs[i + 1];
        int   s2 = g_srcs[i + 2], s3 = g_srcs[i + 3];
        float m0 = g_norms[i],     m1 = g_norms[i + 1];
        float m2 = g_norms[i + 2], m3 = g_norms[i + 3];
        float v0 = xin[s0 * D + lane];
        float v1 = xin[s1 * D + lane];
        float v2 = xin[s2 * D + lane];
        float v3 = xin[s3 * D + lane];
        a = fmaf(v0, m0, a);
        a = fmaf(v1, m1, a);
        a = fmaf(v2, m2, a);
        a = fmaf(v3, m3, a);
    }
    for (; i < end; ++i)
        a = fmaf(xin[g_srcs[i] * D + lane], g_norms[i], a);
    int o = w * D + lane;
    xout[o] = a;
    acc[o] += a;
}

// mean over 4 layer embeddings
__global__ void k_final(float* __restrict__ out, int total) {
    int i = blockIdx.x * blockDim.x + threadIdx.x;
    if (i < total) out[i] *= 0.25f;
}

extern "C" void kernel_launch(void* const* d_in, const int* in_sizes, int n_in,
                              void* d_out, int out_size) {
    const int* ei = (const int*)d_in[0];   // edge_index: int32 (see note above)
    // inputs: edge_index, [n_users, n_items,] user_emb, item_emb
    int iu = (n_in >= 5) ? 3 : 1;
    const float* ue = (const float*)d_in[iu];
    const float* ie = (const float*)d_in[iu + 1];
    int E       = in_sizes[0] / 2;
    int n_users = in_sizes[iu] / D;
    int n_items = in_sizes[iu + 1] / D;
    int n = n_users + n_items;
    float* out = (float*)d_out;

    const int TB = 256;
    int g_nd = (n * D + TB - 1) / TB;

    k_init<<<g_nd, TB>>>(ue, ie, out, n_users, n);
    k_count<<<(E + TB - 1) / TB, TB>>>(ei, E);

    int nb = (n + SCAN_B - 1) / SCAN_B;        // ~293 blocks <= 1024
    k_scan1<<<nb, SCAN_B>>>(n);
    k_scan2<<<1, SCAN_B>>>(nb);
    k_scan3<<<(n + 1 + SCAN_B - 1) / SCAN_B, SCAN_B>>>(n, E);

    k_scatter<<<(E + TB - 1) / TB, TB>>>(ei, E);

    int gp = (n * 32 + TB - 1) / TB;           // one warp per node
    for (int l = 0; l < 3; ++l)
        k_prop<<<gp, TB>>>(l & 1, out, n);

    k_final<<<g_nd, TB>>>(out, n * D);
}

// round 3
// speedup vs baseline: 1.0141x; 1.0141x over previous
#include <cuda_runtime.h>

// LightGCN on GB300 (sm_103a).
// Build CSR indexed by dst (atomic count -> block scan -> scatter of packed
// (src,norm) float2), then 3 atomic-free propagate layers: one warp per dst
// node, 32 lanes = the d=32 embedding row (one 128B line per edge gather).
// x (300k x 32 fp32 = 38.4MB) fits in L2, so gathers run at L2 bandwidth.
// The final /4 is folded into init + prop (no separate mean pass).
// NOTE: edge_index arrives as int32 (JAX x64 disabled downgrades jnp.int64).

#define D       32
#define NMAX    300032
#define EMAX    5000064
#define SCAN_B  1024

__device__ float  g_xa[NMAX * D];   // ping
__device__ float  g_xb[NMAX * D];   // pong
__device__ int    g_degi[NMAX];
__device__ float  g_degf[NMAX];
__device__ int    g_ptr[NMAX + 1];
__device__ int    g_cursor[NMAX];
__device__ float2 g_edge[EMAX];     // .x = src (as int bits), .y = norm
__device__ int    g_bsum[SCAN_B];
__device__ int    g_boff[SCAN_B];

// x0 = concat(user_emb, item_emb); out = 0.25*x0; zero degree counters
__global__ void k_init(const float* __restrict__ ue, const float* __restrict__ ie,
                       float* __restrict__ out, int n_users, int n) {
    int i = blockIdx.x * blockDim.x + threadIdx.x;
    int total = n * D;
    if (i < total) {
        int uend = n_users * D;
        float v = (i < uend) ? ue[i] : ie[i - uend];
        g_xa[i] = v;
        out[i]  = 0.25f * v;
    }
    if (i < n) g_degi[i] = 0;
}

// in-degree of each node over dst (edge_index row 1)
__global__ void k_count(const int* __restrict__ ei, int E) {
    int e = blockIdx.x * blockDim.x + threadIdx.x;
    if (e < E) {
        int dd = ei[E + e];
        if (dd >= 0 && dd < NMAX) atomicAdd(&g_degi[dd], 1);
    }
}

// block-level scan -> exclusive partials in g_ptr, block totals in g_bsum
__global__ void k_scan1(int n) {
    __shared__ int sh[SCAN_B];
    int gid = blockIdx.x * SCAN_B + threadIdx.x;
    int v = (gid < n) ? g_degi[gid] : 0;
    sh[threadIdx.x] = v;
    __syncthreads();
    for (int off = 1; off < SCAN_B; off <<= 1) {
        int t = (threadIdx.x >= off) ? sh[threadIdx.x - off] : 0;
        __syncthreads();
        sh[threadIdx.x] += t;
        __syncthreads();
    }
    if (gid < n) g_ptr[gid] = sh[threadIdx.x] - v;   // exclusive within block
    if (threadIdx.x == SCAN_B - 1) g_bsum[blockIdx.x] = sh[SCAN_B - 1];
}

// scan of block totals (nb <= 1024)
__global__ void k_scan2(int nb) {
    __shared__ int sh[SCAN_B];
    int v = ((int)threadIdx.x < nb) ? g_bsum[threadIdx.x] : 0;
    sh[threadIdx.x] = v;
    __syncthreads();
    for (int off = 1; off < SCAN_B; off <<= 1) {
        int t = (threadIdx.x >= off) ? sh[threadIdx.x - off] : 0;
        __syncthreads();
        sh[threadIdx.x] += t;
        __syncthreads();
    }
    g_boff[threadIdx.x] = sh[threadIdx.x] - v;       // exclusive block offsets
}

// add block offsets; init cursor; float degrees; sentinel ptr[n]=E
__global__ void k_scan3(int n, int E) {
    int gid = blockIdx.x * SCAN_B + threadIdx.x;
    if (gid < n) {
        int p = g_ptr[gid] + g_boff[blockIdx.x];
        g_ptr[gid]    = p;
        g_cursor[gid] = p;
        g_degf[gid]   = (float)g_degi[gid];
    }
    if (gid == n) g_ptr[n] = E;
}

// counting-sort scatter: one packed 8B (src, norm) store per edge
__global__ void k_scatter(const int* __restrict__ ei, int E) {
    int e = blockIdx.x * blockDim.x + threadIdx.x;
    if (e >= E) return;
    int s  = ei[e];
    int dd = ei[E + e];
    if (s < 0 || s >= NMAX || dd < 0 || dd >= NMAX) return;
    int pos = atomicAdd(&g_cursor[dd], 1);
    float dp = g_degf[s] * g_degf[dd];
    float nm = (dp > 0.f) ? rsqrtf(dp) : 0.f;
    g_edge[pos] = make_float2(__int_as_float(s), nm);
}

// one propagate layer: warp per dst node, lane = column. out += 0.25*x_new.
__global__ void k_prop(int sel, float* __restrict__ out, int n) {
    int w    = (blockIdx.x * blockDim.x + threadIdx.x) >> 5;
    int lane = threadIdx.x & 31;
    if (w >= n) return;
    const float*  __restrict__ xin  = sel ? g_xb : g_xa;
    float*        __restrict__ xout = sel ? g_xa : g_xb;
    int i = g_ptr[w], end = g_ptr[w + 1];
    float a = 0.f;
    // unroll 4 edges: 4 independent 128B row gathers in flight per warp
    for (; i + 4 <= end; i += 4) {
        float2 e0 = g_edge[i];
        float2 e1 = g_edge[i + 1];
        float2 e2 = g_edge[i + 2];
        float2 e3 = g_edge[i + 3];
        float v0 = xin[__float_as_int(e0.x) * D + lane];
        float v1 = xin[__float_as_int(e1.x) * D + lane];
        float v2 = xin[__float_as_int(e2.x) * D + lane];
        float v3 = xin[__float_as_int(e3.x) * D + lane];
        a = fmaf(v0, e0.y, a);
        a = fmaf(v1, e1.y, a);
        a = fmaf(v2, e2.y, a);
        a = fmaf(v3, e3.y, a);
    }
    for (; i < end; ++i) {
        float2 e0 = g_edge[i];
        a = fmaf(xin[__float_as_int(e0.x) * D + lane], e0.y, a);
    }
    int o = w * D + lane;
    xout[o] = a;
    out[o] += 0.25f * a;
}

extern "C" void kernel_launch(void* const* d_in, const int* in_sizes, int n_in,
                              void* d_out, int out_size) {
    const int* ei = (const int*)d_in[0];   // edge_index: int32 (see note above)
    // inputs: edge_index, [n_users, n_items,] user_emb, item_emb
    int iu = (n_in >= 5) ? 3 : 1;
    const float* ue = (const float*)d_in[iu];
    const float* ie = (const float*)d_in[iu + 1];
    int E       = in_sizes[0] / 2;
    int n_users = in_sizes[iu] / D;
    int n_items = in_sizes[iu + 1] / D;
    int n = n_users + n_items;
    float* out = (float*)d_out;

    const int TB = 256;
    int g_nd = (n * D + TB - 1) / TB;

    k_init<<<g_nd, TB>>>(ue, ie, out, n_users, n);
    k_count<<<(E + TB - 1) / TB, TB>>>(ei, E);

    int nb = (n + SCAN_B - 1) / SCAN_B;        // ~293 blocks <= 1024
    k_scan1<<<nb, SCAN_B>>>(n);
    k_scan2<<<1, SCAN_B>>>(nb);
    k_scan3<<<(n + 1 + SCAN_B - 1) / SCAN_B, SCAN_B>>>(n, E);

    k_scatter<<<(E + TB - 1) / TB, TB>>>(ei, E);

    int gp = (n * 32 + TB - 1) / TB;           // one warp per node
    for (int l = 0; l < 3; ++l)
        k_prop<<<gp, TB>>>(l & 1, out, n);
}